// round 6
// baseline (speedup 1.0000x reference)
#include <cuda_runtime.h>
#include <cuda_bf16.h>
#include <math.h>
#include <stdint.h>

#define T_TOK 2048
#define D     1024
#define DM    4096
#define E     8
#define CAP   2048

// ---------------- device scratch (static: allocation-guard safe) ----------------
__device__ int   g_cnt[E];
__device__ int   g_tok[E * CAP];
__device__ float g_wt [E * CAP];
__device__ __nv_bfloat16 g_xhi[T_TOK * D];
__device__ __nv_bfloat16 g_xlo[T_TOK * D];
__device__ __nv_bfloat16 g_hhi[(size_t)E * CAP * DM];
__device__ __nv_bfloat16 g_hlo[(size_t)E * CAP * DM];
// Tiled split-bf16 weights:
//  g_wu: per (e, nb(32), it(16)) 64KB block: bufs [Ghi0,Ghi1,Glo0,Glo1,Ihi0,Ihi1,Ilo0,Ilo1],
//        each buf = 64 k-rows x 64 cols x 2B = 8192B (rows 128B packed)
__device__ __align__(256) uint8_t g_wu[(size_t)268435456];
//  g_wd: per (e, nb(4), it(64)) 64KB block: bufs [hi q0..q3, lo q0..q3]
__device__ __align__(256) uint8_t g_wd[(size_t)134217728];

// ---------------- helpers ----------------
__device__ __forceinline__ uint32_t smem_u32(const void* p) {
    uint32_t a;
    asm("{ .reg .u64 t; cvta.to.shared.u64 t, %1; cvt.u32.u64 %0, t; }" : "=r"(a) : "l"(p));
    return a;
}
__device__ __forceinline__ void split2(float v, __nv_bfloat16& h, __nv_bfloat16& l) {
    h = __float2bfloat16(v);
    l = __float2bfloat16(v - __bfloat162float(h));
}
__device__ __forceinline__ uint32_t packbf(__nv_bfloat16 a, __nv_bfloat16 b) {
    __nv_bfloat162 t = __halves2bfloat162(a, b);
    return *reinterpret_cast<uint32_t*>(&t);
}
__device__ __forceinline__ void cv8(float4 a, float4 b, uint4& uh, uint4& ul) {
    __nv_bfloat16 h0, l0, h1, l1, h2, l2, h3, l3;
    split2(a.x, h0, l0); split2(a.y, h1, l1); split2(a.z, h2, l2); split2(a.w, h3, l3);
    uh.x = packbf(h0, h1); uh.y = packbf(h2, h3);
    ul.x = packbf(l0, l1); ul.y = packbf(l2, l3);
    split2(b.x, h0, l0); split2(b.y, h1, l1); split2(b.z, h2, l2); split2(b.w, h3, l3);
    uh.z = packbf(h0, h1); uh.w = packbf(h2, h3);
    ul.z = packbf(l0, l1); ul.w = packbf(l2, l3);
}
__device__ __forceinline__ void ldsm4(uint32_t (&r)[4], uint32_t addr) {
    asm volatile("ldmatrix.sync.aligned.m8n8.x4.shared.b16 {%0,%1,%2,%3}, [%4];"
        : "=r"(r[0]), "=r"(r[1]), "=r"(r[2]), "=r"(r[3]) : "r"(addr));
}
__device__ __forceinline__ void ldsm4t(uint32_t (&r)[4], uint32_t addr) {
    asm volatile("ldmatrix.sync.aligned.m8n8.x4.trans.shared.b16 {%0,%1,%2,%3}, [%4];"
        : "=r"(r[0]), "=r"(r[1]), "=r"(r[2]), "=r"(r[3]) : "r"(addr));
}
__device__ __forceinline__ void mma16816(float* d, const uint32_t (&a)[4],
                                         uint32_t b0, uint32_t b1) {
    asm volatile(
        "mma.sync.aligned.m16n8k16.row.col.f32.bf16.bf16.f32 "
        "{%0,%1,%2,%3}, {%4,%5,%6,%7}, {%8,%9}, {%0,%1,%2,%3};"
        : "+f"(d[0]), "+f"(d[1]), "+f"(d[2]), "+f"(d[3])
        : "r"(a[0]), "r"(a[1]), "r"(a[2]), "r"(a[3]), "r"(b0), "r"(b1));
}
__device__ __forceinline__ void cpa16(uint32_t s, const void* g) {
    asm volatile("cp.async.cg.shared.global [%0], [%1], 16;" :: "r"(s), "l"(g));
}
#define CP_COMMIT() asm volatile("cp.async.commit_group;" ::: "memory")
#define CP_WAITALL() asm volatile("cp.async.wait_group 0;" ::: "memory")

// stage layout (bytes), identical for both GEMM kernels:
//   A hi [0,18432)  (128 rows x 144B: 128B data + 16 pad)
//   A lo [18432,36864)
//   B bufs [36864, 36864+8*9216): buf i = 64 rows x 144B (128B data + 16 pad)
#define STG     110592
#define SMEMSZ  (2 * STG)

// ---------------------------------------------------------------
__global__ void zero_cnt_kernel() {
    if (threadIdx.x < E) g_cnt[threadIdx.x] = 0;
}

__global__ void convert_x_kernel(const float4* __restrict__ x4) {
    int i = blockIdx.x * blockDim.x + threadIdx.x;
    float4 v = x4[i];
    __nv_bfloat16 h0, h1, h2, h3, l0, l1, l2, l3;
    split2(v.x, h0, l0); split2(v.y, h1, l1);
    split2(v.z, h2, l2); split2(v.w, h3, l3);
    ((uint2*)g_xhi)[i] = make_uint2(packbf(h0, h1), packbf(h2, h3));
    ((uint2*)g_xlo)[i] = make_uint2(packbf(l0, l1), packbf(l2, l3));
}

// Pre-convert up weights (Wgate, Win) fp32 -> tiled split-bf16 blocks.
__global__ void conv_up_kernel(const float* __restrict__ Wg, const float* __restrict__ Wi) {
    size_t t = (size_t)blockIdx.x * 256 + threadIdx.x;   // 8.39M threads
    uint32_t blk = (uint32_t)(t >> 11);                  // 4096 blocks of 64KB
    uint32_t w   = (uint32_t)t & 2047;
    uint32_t p   = w >> 9;                               // 0..3: mat=p>>1, half=p&1
    uint32_t cin = w & 511;                              // 16B chunk in buf
    uint32_t k   = cin >> 3, c8 = cin & 7;
    uint32_t e = blk >> 9, nb = (blk >> 4) & 31, it = blk & 15;
    const float* W = (p & 2) ? Wi : Wg;
    const float* src = W + ((size_t)e * D + it * 64 + k) * DM + nb * 128 + (p & 1) * 64 + c8 * 8;
    float4 v0 = *(const float4*)src, v1 = *(const float4*)(src + 4);
    uint4 uh, ul; cv8(v0, v1, uh, ul);
    uint8_t* base = g_wu + (size_t)blk * 65536;
    uint32_t bhi = (p >> 1) * 4 + (p & 1);
    *(uint4*)(base + bhi * 8192 + cin * 16)       = uh;
    *(uint4*)(base + (bhi + 2) * 8192 + cin * 16) = ul;
}

// Pre-convert down weights (Wout).
__global__ void conv_dn_kernel(const float* __restrict__ Wo) {
    size_t t = (size_t)blockIdx.x * 256 + threadIdx.x;   // 4.19M threads
    uint32_t blk = (uint32_t)(t >> 11);                  // 2048 blocks
    uint32_t w   = (uint32_t)t & 2047;
    uint32_t p   = w >> 9;                               // n-quarter 0..3
    uint32_t cin = w & 511;
    uint32_t k   = cin >> 3, c8 = cin & 7;
    uint32_t e = blk >> 8, nb = (blk >> 6) & 3, it = blk & 63;
    const float* src = Wo + ((size_t)e * DM + it * 64 + k) * D + nb * 256 + p * 64 + c8 * 8;
    float4 v0 = *(const float4*)src, v1 = *(const float4*)(src + 4);
    uint4 uh, ul; cv8(v0, v1, uh, ul);
    uint8_t* base = g_wd + (size_t)blk * 65536;
    *(uint4*)(base + p * 8192 + cin * 16)       = uh;
    *(uint4*)(base + (p + 4) * 8192 + cin * 16) = ul;
}

__global__ void router_kernel(const float* __restrict__ x,
                              const float* __restrict__ Wg) {
    int t = blockIdx.x;
    int lane = threadIdx.x & 31;
    int w = threadIdx.x >> 5;
    const float* h = x + (size_t)t * D;
    float s = 0.f;
    for (int i = lane; i < D; i += 32) s += h[i] * Wg[i * E + w];
    #pragma unroll
    for (int o = 16; o; o >>= 1) s += __shfl_xor_sync(0xffffffffu, s, o);
    __shared__ float logits[E];
    if (lane == 0) logits[w] = s;
    __syncthreads();
    if (threadIdx.x == 0) {
        float m = -1e30f;
        #pragma unroll
        for (int e = 0; e < E; e++) m = fmaxf(m, logits[e]);
        float p[E];
        #pragma unroll
        for (int e = 0; e < E; e++) p[e] = expf(logits[e] - m);
        int e0 = 0;
        #pragma unroll
        for (int e = 1; e < E; e++) if (p[e] > p[e0]) e0 = e;
        int e1 = (e0 == 0) ? 1 : 0;
        #pragma unroll
        for (int e = 0; e < E; e++) { if (e == e0) continue; if (p[e] > p[e1]) e1 = e; }
        float rs = 1.f / (p[e0] + p[e1]);
        int i0 = atomicAdd(&g_cnt[e0], 1);
        g_tok[e0 * CAP + i0] = t;  g_wt[e0 * CAP + i0] = p[e0] * rs;
        int i1 = atomicAdd(&g_cnt[e1], 1);
        g_tok[e1 * CAP + i1] = t;  g_wt[e1 * CAP + i1] = p[e1] * rs;
    }
}

// ---------------------------------------------------------------
// Up-proj: M128 x N128 (G and I each), BK=64, pure cp.async pipeline.
__global__ void __launch_bounds__(256, 1)
moe_up_kernel() {
    extern __shared__ char smem[];
    uint32_t sb = smem_u32(smem);

    int e = blockIdx.z;
    int cnt = g_cnt[e];
    int row0 = blockIdx.x * 128;
    if (row0 >= cnt) return;
    int nby = blockIdx.y;
    int n0 = nby * 128;

    int tid = threadIdx.x, wid = tid >> 5, lane = tid & 31;
    int warp_m = wid >> 2, warp_n = wid & 3;

    // A loader: thread -> (row, split), 8 x 16B per iter
    int arow = tid & 127, asplit = tid >> 7;
    int tok = g_tok[e * CAP + min(row0 + arow, cnt - 1)];
    const char* srcA = (const char*)((asplit ? g_xlo : g_xhi) + (size_t)tok * D);
    uint32_t dstA = sb + asplit * 18432 + arow * 144;

    // B loader: 16 x 16B chunks per iter from tiled g_wu
    const uint8_t* srcB = g_wu + (size_t)((e * 32 + nby) * 16) * 65536;

    // fragment addresses
    uint32_t aB = sb + (warp_m * 64 + (lane & 15)) * 144 + (lane >> 4) * 16;
    uint32_t bB = sb + 36864 + (lane & 15) * 144 + ((warp_n & 1) * 32 + (lane >> 4) * 8) * 2;
    uint32_t halfoff = (uint32_t)(warp_n >> 1) * 9216;

    float acc[2][4][4][4];
    #pragma unroll
    for (int a = 0; a < 2; a++)
        #pragma unroll
        for (int b = 0; b < 4; b++)
            #pragma unroll
            for (int c = 0; c < 4; c++)
                #pragma unroll
                for (int d = 0; d < 4; d++) acc[a][b][c][d] = 0.f;

    const int NIT = D / 64;   // 16

    #define CPA_UP(ST, IT) do { \
        const char* _a = srcA + (size_t)(IT) * 128; \
        uint32_t _d = dstA + (ST); \
        _Pragma("unroll") \
        for (int _j = 0; _j < 8; _j++) cpa16(_d + _j * 16, _a + _j * 16); \
        const uint8_t* _b = srcB + (size_t)(IT) * 65536; \
        _Pragma("unroll") \
        for (int _j = 0; _j < 16; _j++) { \
            uint32_t _c = (uint32_t)tid + _j * 256; \
            uint32_t _dd = sb + (ST) + 36864 + (_c >> 9) * 9216 \
                         + ((_c & 511) >> 3) * 144 + (_c & 7) * 16; \
            cpa16(_dd, _b + _c * 16); \
        } \
    } while (0)

    CPA_UP(0, 0); CP_COMMIT();

    for (int it = 0; it < NIT; ++it) {
        uint32_t ps = (uint32_t)(it & 1) * STG;
        uint32_t qs = STG - ps;
        CP_WAITALL();
        __syncthreads();
        if (it + 1 < NIT) CPA_UP(qs, it + 1);
        CP_COMMIT();

        #pragma unroll
        for (int kk = 0; kk < 4; kk++) {
            uint32_t Ah[4][4], Al[4][4];
            #pragma unroll
            for (int f = 0; f < 4; f++) {
                ldsm4(Ah[f], aB + ps + f * 2304 + kk * 32);
                ldsm4(Al[f], aB + ps + 18432 + f * 2304 + kk * 32);
            }
            #pragma unroll
            for (int mat = 0; mat < 2; mat++) {
                #pragma unroll
                for (int jt = 0; jt < 2; jt++) {
                    uint32_t bh[4], bl[4];
                    uint32_t bb = bB + ps + (uint32_t)mat * 36864 + halfoff + kk * 2304 + jt * 32;
                    ldsm4t(bh, bb);
                    ldsm4t(bl, bb + 18432);
                    #pragma unroll
                    for (int f = 0; f < 4; f++) {
                        mma16816(acc[mat][f][2*jt],   Ah[f], bh[0], bh[1]);
                        mma16816(acc[mat][f][2*jt+1], Ah[f], bh[2], bh[3]);
                        mma16816(acc[mat][f][2*jt],   Ah[f], bl[0], bl[1]);
                        mma16816(acc[mat][f][2*jt+1], Ah[f], bl[2], bl[3]);
                        mma16816(acc[mat][f][2*jt],   Al[f], bh[0], bh[1]);
                        mma16816(acc[mat][f][2*jt+1], Al[f], bh[2], bh[3]);
                    }
                }
            }
        }
    }
    #undef CPA_UP

    // epilogue: silu(G)*I -> split bf16 -> g_hhi/g_hlo
    #pragma unroll
    for (int f = 0; f < 4; f++) {
        #pragma unroll
        for (int h = 0; h < 2; h++) {
            int r = row0 + warp_m * 64 + f * 16 + (lane >> 2) + h * 8;
            if (r >= cnt) continue;
            size_t base = (size_t)(e * CAP + r) * DM;
            int col = n0 + warp_n * 32 + (lane & 3) * 2;
            #pragma unroll
            for (int n8 = 0; n8 < 4; n8++) {
                float g0 = acc[0][f][n8][2*h], g1 = acc[0][f][n8][2*h+1];
                float i0 = acc[1][f][n8][2*h], i1 = acc[1][f][n8][2*h+1];
                float v0 = g0 / (1.f + __expf(-g0)) * i0;
                float v1 = g1 / (1.f + __expf(-g1)) * i1;
                __nv_bfloat16 h0, l0, h1, l1;
                split2(v0, h0, l0); split2(v1, h1, l1);
                *(uint32_t*)(g_hhi + base + col + n8 * 8) = packbf(h0, h1);
                *(uint32_t*)(g_hlo + base + col + n8 * 8) = packbf(l0, l1);
            }
        }
    }
}

// ---------------------------------------------------------------
// Down-proj + scatter: M128 x N256, BK=64, warp tile m64 x n64.
__global__ void __launch_bounds__(256, 1)
moe_dn_kernel(float* __restrict__ out) {
    extern __shared__ char smem[];
    uint32_t sb = smem_u32(smem);

    int e = blockIdx.z;
    int cnt = g_cnt[e];
    int row0 = blockIdx.x * 128;
    if (row0 >= cnt) return;
    int nby = blockIdx.y;
    int n0 = nby * 256;

    int tid = threadIdx.x, wid = tid >> 5, lane = tid & 31;
    int warp_m = wid >> 2, warp_n = wid & 3;

    int arow = tid & 127, asplit = tid >> 7;
    size_t hrow = (size_t)(e * CAP + min(row0 + arow, cnt - 1)) * DM;
    const char* srcA = (const char*)((asplit ? g_hlo : g_hhi) + hrow);
    uint32_t dstA = sb + asplit * 18432 + arow * 144;

    const uint8_t* srcB = g_wd + (size_t)((e * 4 + nby) * 64) * 65536;

    uint32_t aB = sb + (warp_m * 64 + (lane & 15)) * 144 + (lane >> 4) * 16;
    uint32_t bB = sb + 36864 + (uint32_t)warp_n * 9216 + (lane & 15) * 144 + (lane >> 4) * 16;

    float acc[4][8][4];
    #pragma unroll
    for (int a = 0; a < 4; a++)
        #pragma unroll
        for (int b = 0; b < 8; b++)
            #pragma unroll
            for (int c = 0; c < 4; c++) acc[a][b][c] = 0.f;

    const int NIT = DM / 64;   // 64

    #define CPA_DN(ST, IT) do { \
        const char* _a = srcA + (size_t)(IT) * 128; \
        uint32_t _d = dstA + (ST); \
        _Pragma("unroll") \
        for (int _j = 0; _j < 8; _j++) cpa16(_d + _j * 16, _a + _j * 16); \
        const uint8_t* _b = srcB + (size_t)(IT) * 65536; \
        _Pragma("unroll") \
        for (int _j = 0; _j < 16; _j++) { \
            uint32_t _c = (uint32_t)tid + _j * 256; \
            uint32_t _dd = sb + (ST) + 36864 + (_c >> 9) * 9216 \
                         + ((_c & 511) >> 3) * 144 + (_c & 7) * 16; \
            cpa16(_dd, _b + _c * 16); \
        } \
    } while (0)

    CPA_DN(0, 0); CP_COMMIT();

    for (int it = 0; it < NIT; ++it) {
        uint32_t ps = (uint32_t)(it & 1) * STG;
        uint32_t qs = STG - ps;
        CP_WAITALL();
        __syncthreads();
        if (it + 1 < NIT) CPA_DN(qs, it + 1);
        CP_COMMIT();

        #pragma unroll
        for (int kk = 0; kk < 4; kk++) {
            uint32_t Ah[4][4], Al[4][4];
            #pragma unroll
            for (int f = 0; f < 4; f++) {
                ldsm4(Ah[f], aB + ps + f * 2304 + kk * 32);
                ldsm4(Al[f], aB + ps + 18432 + f * 2304 + kk * 32);
            }
            #pragma unroll
            for (int jt = 0; jt < 4; jt++) {
                uint32_t bh[4], bl[4];
                uint32_t bb = bB + ps + kk * 2304 + jt * 32;
                ldsm4t(bh, bb);
                ldsm4t(bl, bb + 36864);
                #pragma unroll
                for (int f = 0; f < 4; f++) {
                    mma16816(acc[f][2*jt],   Ah[f], bh[0], bh[1]);
                    mma16816(acc[f][2*jt+1], Ah[f], bh[2], bh[3]);
                    mma16816(acc[f][2*jt],   Ah[f], bl[0], bl[1]);
                    mma16816(acc[f][2*jt+1], Ah[f], bl[2], bl[3]);
                    mma16816(acc[f][2*jt],   Al[f], bh[0], bh[1]);
                    mma16816(acc[f][2*jt+1], Al[f], bh[2], bh[3]);
                }
            }
        }
    }
    #undef CPA_DN

    #pragma unroll
    for (int f = 0; f < 4; f++) {
        #pragma unroll
        for (int h = 0; h < 2; h++) {
            int r = row0 + warp_m * 64 + f * 16 + (lane >> 2) + h * 8;
            if (r >= cnt) continue;
            int   tk = g_tok[e * CAP + r];
            float wt = g_wt [e * CAP + r];
            float* po = out + (size_t)tk * D + n0 + warp_n * 64 + (lane & 3) * 2;
            #pragma unroll
            for (int n8 = 0; n8 < 8; n8++) {
                atomicAdd(po + n8 * 8,     acc[f][n8][2*h]     * wt);
                atomicAdd(po + n8 * 8 + 1, acc[f][n8][2*h + 1] * wt);
            }
        }
    }
}

// ---------------------------------------------------------------
extern "C" void kernel_launch(void* const* d_in, const int* in_sizes, int n_in,
                              void* d_out, int out_size) {
    const float* x   = (const float*)d_in[0];
    const float* Wg  = (const float*)d_in[1];
    const float* Weg = (const float*)d_in[2];
    const float* Wei = (const float*)d_in[3];
    const float* Weo = (const float*)d_in[4];
    float* out = (float*)d_out;

    static int attr_set = 0;
    if (!attr_set) {
        cudaFuncSetAttribute(moe_up_kernel, cudaFuncAttributeMaxDynamicSharedMemorySize, SMEMSZ);
        cudaFuncSetAttribute(moe_dn_kernel, cudaFuncAttributeMaxDynamicSharedMemorySize, SMEMSZ);
        attr_set = 1;
    }

    cudaMemsetAsync(out, 0, (size_t)out_size * sizeof(float));
    zero_cnt_kernel<<<1, 32>>>();
    conv_up_kernel<<<32768, 256>>>(Weg, Wei);
    conv_dn_kernel<<<16384, 256>>>(Weo);
    convert_x_kernel<<<(T_TOK * D / 4) / 256, 256>>>((const float4*)x);
    router_kernel<<<T_TOK, 256>>>(x, Wg);
    moe_up_kernel<<<dim3(CAP / 128, DM / 128, E), 256, SMEMSZ>>>();
    moe_dn_kernel<<<dim3(CAP / 128, D / 256, E), 256, SMEMSZ>>>(out);
}

// round 7
// speedup vs baseline: 1.2066x; 1.2066x over previous
#include <cuda_runtime.h>
#include <cuda_bf16.h>
#include <math.h>
#include <stdint.h>

#define T_TOK 2048
#define D     1024
#define DM    4096
#define E     8
#define CAP   2048

// ---------------- device scratch (static: allocation-guard safe) ----------------
__device__ int   g_cnt[E];
__device__ int   g_tok[E * CAP];
__device__ float g_wt [E * CAP];
__device__ __nv_bfloat16 g_xhi[T_TOK * D];
__device__ __nv_bfloat16 g_xlo[T_TOK * D];
__device__ __nv_bfloat16 g_hhi[(size_t)E * CAP * DM];
__device__ __nv_bfloat16 g_hlo[(size_t)E * CAP * DM];

// ---------------- helpers ----------------
__device__ __forceinline__ uint32_t smem_u32(const void* p) {
    uint32_t a;
    asm("{ .reg .u64 t; cvta.to.shared.u64 t, %1; cvt.u32.u64 %0, t; }" : "=r"(a) : "l"(p));
    return a;
}
__device__ __forceinline__ void split2(float v, __nv_bfloat16& h, __nv_bfloat16& l) {
    h = __float2bfloat16(v);
    l = __float2bfloat16(v - __bfloat162float(h));
}
__device__ __forceinline__ uint32_t packbf(__nv_bfloat16 a, __nv_bfloat16 b) {
    __nv_bfloat162 t = __halves2bfloat162(a, b);
    return *reinterpret_cast<uint32_t*>(&t);
}
__device__ __forceinline__ void cv8(float4 a, float4 b, uint4& uh, uint4& ul) {
    __nv_bfloat16 h0, l0, h1, l1, h2, l2, h3, l3;
    split2(a.x, h0, l0); split2(a.y, h1, l1); split2(a.z, h2, l2); split2(a.w, h3, l3);
    uh.x = packbf(h0, h1); uh.y = packbf(h2, h3);
    ul.x = packbf(l0, l1); ul.y = packbf(l2, l3);
    split2(b.x, h0, l0); split2(b.y, h1, l1); split2(b.z, h2, l2); split2(b.w, h3, l3);
    uh.z = packbf(h0, h1); uh.w = packbf(h2, h3);
    ul.z = packbf(l0, l1); ul.w = packbf(l2, l3);
}
__device__ __forceinline__ void ldsm4(uint32_t (&r)[4], uint32_t addr) {
    asm volatile("ldmatrix.sync.aligned.m8n8.x4.shared.b16 {%0,%1,%2,%3}, [%4];"
        : "=r"(r[0]), "=r"(r[1]), "=r"(r[2]), "=r"(r[3]) : "r"(addr));
}
__device__ __forceinline__ void ldsm4t(uint32_t (&r)[4], uint32_t addr) {
    asm volatile("ldmatrix.sync.aligned.m8n8.x4.trans.shared.b16 {%0,%1,%2,%3}, [%4];"
        : "=r"(r[0]), "=r"(r[1]), "=r"(r[2]), "=r"(r[3]) : "r"(addr));
}
__device__ __forceinline__ void mma16816(float* d, const uint32_t (&a)[4],
                                         uint32_t b0, uint32_t b1) {
    asm volatile(
        "mma.sync.aligned.m16n8k16.row.col.f32.bf16.bf16.f32 "
        "{%0,%1,%2,%3}, {%4,%5,%6,%7}, {%8,%9}, {%0,%1,%2,%3};"
        : "+f"(d[0]), "+f"(d[1]), "+f"(d[2]), "+f"(d[3])
        : "r"(a[0]), "r"(a[1]), "r"(a[2]), "r"(a[3]), "r"(b0), "r"(b1));
}
__device__ __forceinline__ void cpa16(uint32_t s, const void* g) {
    asm volatile("cp.async.cg.shared.global [%0], [%1], 16;" :: "r"(s), "l"(g));
}
#define CP_COMMIT() asm volatile("cp.async.commit_group;" ::: "memory")
#define CP_WAIT0()  asm volatile("cp.async.wait_group 0;" ::: "memory")

// stage layout (bytes), identical for both kernels:
//   A hi [0,10240)  A lo [10240,20480)  B region [20480, 20480+36864)
#define STAGE   57344
#define SMEMSZ  (2 * STAGE)

// ---------------------------------------------------------------
__global__ void zero_cnt_kernel() {
    if (threadIdx.x < E) g_cnt[threadIdx.x] = 0;
}

__global__ void convert_x_kernel(const float4* __restrict__ x4) {
    int i = blockIdx.x * blockDim.x + threadIdx.x;
    float4 v = x4[i];
    __nv_bfloat16 h0, h1, h2, h3, l0, l1, l2, l3;
    split2(v.x, h0, l0); split2(v.y, h1, l1);
    split2(v.z, h2, l2); split2(v.w, h3, l3);
    ((uint2*)g_xhi)[i] = make_uint2(packbf(h0, h1), packbf(h2, h3));
    ((uint2*)g_xlo)[i] = make_uint2(packbf(l0, l1), packbf(l2, l3));
}

__global__ void router_kernel(const float* __restrict__ x,
                              const float* __restrict__ Wg) {
    int t = blockIdx.x;
    int lane = threadIdx.x & 31;
    int w = threadIdx.x >> 5;
    const float* h = x + (size_t)t * D;
    float s = 0.f;
    for (int i = lane; i < D; i += 32) s += h[i] * Wg[i * E + w];
    #pragma unroll
    for (int o = 16; o; o >>= 1) s += __shfl_xor_sync(0xffffffffu, s, o);
    __shared__ float logits[E];
    if (lane == 0) logits[w] = s;
    __syncthreads();
    if (threadIdx.x == 0) {
        float m = -1e30f;
        #pragma unroll
        for (int e = 0; e < E; e++) m = fmaxf(m, logits[e]);
        float p[E];
        #pragma unroll
        for (int e = 0; e < E; e++) p[e] = expf(logits[e] - m);
        int e0 = 0;
        #pragma unroll
        for (int e = 1; e < E; e++) if (p[e] > p[e0]) e0 = e;
        int e1 = (e0 == 0) ? 1 : 0;
        #pragma unroll
        for (int e = 0; e < E; e++) { if (e == e0) continue; if (p[e] > p[e1]) e1 = e; }
        float rs = 1.f / (p[e0] + p[e1]);
        int i0 = atomicAdd(&g_cnt[e0], 1);
        g_tok[e0 * CAP + i0] = t;  g_wt[e0 * CAP + i0] = p[e0] * rs;
        int i1 = atomicAdd(&g_cnt[e1], 1);
        g_tok[e1 * CAP + i1] = t;  g_wt[e1 * CAP + i1] = p[e1] * rs;
    }
}

// ---------------------------------------------------------------
// Up-proj: M128 x N128 (G and I each), 8 warps, warp tile m64 x n32 (both mats).
__global__ void __launch_bounds__(256, 1)
moe_up_kernel(const float* __restrict__ Wgate, const float* __restrict__ Win) {
    extern __shared__ char smem[];
    uint32_t sb = smem_u32(smem);

    int e = blockIdx.z;
    int cnt = g_cnt[e];
    int row0 = blockIdx.x * 128;
    if (row0 >= cnt) return;
    int n0 = blockIdx.y * 128;

    int tid = threadIdx.x, wid = tid >> 5, lane = tid & 31;
    int warp_m = wid >> 2, warp_n = wid & 3;

    // A loader: row rA, chunks q0,q0+1 (16B each) per split
    int rA = tid >> 1, q0 = (tid & 1) * 2;
    int tok = g_tok[e * CAP + min(row0 + rA, cnt - 1)];
    const char* gAh = (const char*)(g_xhi + (size_t)tok * D) + q0 * 16;
    const char* gAl = (const char*)(g_xlo + (size_t)tok * D) + q0 * 16;
    uint32_t sA = rA * 80 + q0 * 16;

    // B loader
    int bk = tid >> 3, bn = (tid & 7) * 8;
    const float* pG = Wgate + (size_t)e * D * DM + (size_t)bk * DM + n0 + bn;
    const float* pI = Win   + (size_t)e * D * DM + (size_t)bk * DM + n0 + bn;
    uint32_t sB = 20480 + bk * 144 + bn * 2;

    // compute base addresses (relative; add stage offset ps)
    uint32_t aB = sb + (warp_m * 64 + (lane & 15)) * 80 + (lane >> 4) * 16;
    uint32_t bB = sb + 20480 + (warp_n >> 1) * 4608 + (lane & 15) * 144
                + ((warp_n & 1) * 32 + (lane >> 4) * 8) * 2;

    float acc[2][4][4][4];
    #pragma unroll
    for (int a = 0; a < 2; a++)
        #pragma unroll
        for (int b = 0; b < 4; b++)
            #pragma unroll
            for (int c = 0; c < 4; c++)
                #pragma unroll
                for (int d = 0; d < 4; d++) acc[a][b][c][d] = 0.f;

    const int NIT = D / 32;   // 32
    float4 vg[4], vi[4];

    #define LDW_UP(IT) do { \
        const float* _g = pG + (size_t)(IT) * 32 * DM; \
        const float* _i = pI + (size_t)(IT) * 32 * DM; \
        vg[0] = *(const float4*)_g;        vg[1] = *(const float4*)(_g + 4); \
        vg[2] = *(const float4*)(_g + 64); vg[3] = *(const float4*)(_g + 68); \
        vi[0] = *(const float4*)_i;        vi[1] = *(const float4*)(_i + 4); \
        vi[2] = *(const float4*)(_i + 64); vi[3] = *(const float4*)(_i + 68); \
    } while (0)

    #define STW_UP(ST) do { \
        uint4 uh, ul; \
        cv8(vg[0], vg[1], uh, ul); \
        *(uint4*)(smem + (ST) + sB)          = uh; \
        *(uint4*)(smem + (ST) + sB + 9216)   = ul; \
        cv8(vg[2], vg[3], uh, ul); \
        *(uint4*)(smem + (ST) + sB + 4608)   = uh; \
        *(uint4*)(smem + (ST) + sB + 13824)  = ul; \
        cv8(vi[0], vi[1], uh, ul); \
        *(uint4*)(smem + (ST) + sB + 18432)  = uh; \
        *(uint4*)(smem + (ST) + sB + 27648)  = ul; \
        cv8(vi[2], vi[3], uh, ul); \
        *(uint4*)(smem + (ST) + sB + 23040)  = uh; \
        *(uint4*)(smem + (ST) + sB + 32256)  = ul; \
    } while (0)

    #define CPA_T(ST, IT) do { \
        uint32_t _d = sb + (ST) + sA; \
        const char* _ah = gAh + (size_t)(IT) * 64; \
        const char* _al = gAl + (size_t)(IT) * 64; \
        cpa16(_d, _ah);          cpa16(_d + 16, _ah + 16); \
        cpa16(_d + 10240, _al);  cpa16(_d + 10240 + 16, _al + 16); \
    } while (0)

    // prologue
    LDW_UP(0); STW_UP(0); CPA_T(0, 0); CP_COMMIT();
    LDW_UP(1);
    CP_WAIT0();
    __syncthreads();

    for (int it = 0; it < NIT; ++it) {
        uint32_t ps = (uint32_t)(it & 1) * STAGE;
        uint32_t qs = STAGE - ps;
        bool m1 = (it + 1 < NIT);
        if (m1) { STW_UP(qs); CPA_T(qs, it + 1); }
        CP_COMMIT();
        if (it + 2 < NIT) LDW_UP(it + 2);

        #pragma unroll
        for (int kk = 0; kk < 2; kk++) {
            uint32_t Ah[4][4], Al[4][4];
            #pragma unroll
            for (int f = 0; f < 4; f++) {
                ldsm4(Ah[f], aB + ps + f * 1280 + kk * 32);
                ldsm4(Al[f], aB + ps + 10240 + f * 1280 + kk * 32);
            }
            #pragma unroll
            for (int mat = 0; mat < 2; mat++) {
                uint32_t sec = ps + mat * 18432 + kk * 2304;
                #pragma unroll
                for (int jt = 0; jt < 2; jt++) {
                    uint32_t bh[4], bl[4];
                    ldsm4t(bh, bB + sec + jt * 32);
                    ldsm4t(bl, bB + sec + 9216 + jt * 32);
                    // product-major order: same-acc reuse distance = 8 MMAs
                    #pragma unroll
                    for (int f = 0; f < 4; f++) {
                        mma16816(acc[mat][f][2*jt],   Ah[f], bh[0], bh[1]);
                        mma16816(acc[mat][f][2*jt+1], Ah[f], bh[2], bh[3]);
                    }
                    #pragma unroll
                    for (int f = 0; f < 4; f++) {
                        mma16816(acc[mat][f][2*jt],   Ah[f], bl[0], bl[1]);
                        mma16816(acc[mat][f][2*jt+1], Ah[f], bl[2], bl[3]);
                    }
                    #pragma unroll
                    for (int f = 0; f < 4; f++) {
                        mma16816(acc[mat][f][2*jt],   Al[f], bh[0], bh[1]);
                        mma16816(acc[mat][f][2*jt+1], Al[f], bh[2], bh[3]);
                    }
                }
            }
        }
        if (m1) CP_WAIT0();
        __syncthreads();
    }

    // epilogue: silu(G)*I -> split bf16 -> g_hhi/g_hlo
    #pragma unroll
    for (int f = 0; f < 4; f++) {
        #pragma unroll
        for (int h = 0; h < 2; h++) {
            int r = row0 + warp_m * 64 + f * 16 + (lane >> 2) + h * 8;
            if (r >= cnt) continue;
            size_t base = (size_t)(e * CAP + r) * DM;
            int col = n0 + warp_n * 32 + (lane & 3) * 2;
            #pragma unroll
            for (int n8 = 0; n8 < 4; n8++) {
                float g0 = acc[0][f][n8][2*h], g1 = acc[0][f][n8][2*h+1];
                float i0 = acc[1][f][n8][2*h], i1 = acc[1][f][n8][2*h+1];
                float v0 = g0 / (1.f + __expf(-g0)) * i0;
                float v1 = g1 / (1.f + __expf(-g1)) * i1;
                __nv_bfloat16 h0, l0, h1, l1;
                split2(v0, h0, l0); split2(v1, h1, l1);
                *(uint32_t*)(g_hhi + base + col + n8 * 8) = packbf(h0, h1);
                *(uint32_t*)(g_hlo + base + col + n8 * 8) = packbf(l0, l1);
            }
        }
    }
    #undef LDW_UP
    #undef STW_UP
}

// ---------------------------------------------------------------
// Down-proj + scatter: M128 x N256 tile, 8 warps, warp tile m64 x n64.
__global__ void __launch_bounds__(256, 1)
moe_dn_kernel(const float* __restrict__ Wout, float* __restrict__ out) {
    extern __shared__ char smem[];
    uint32_t sb = smem_u32(smem);

    int e = blockIdx.z;
    int cnt = g_cnt[e];
    int row0 = blockIdx.x * 128;
    if (row0 >= cnt) return;
    int n0 = blockIdx.y * 256;

    int tid = threadIdx.x, wid = tid >> 5, lane = tid & 31;
    int warp_m = wid >> 2, warp_n = wid & 3;

    int rA = tid >> 1, q0 = (tid & 1) * 2;
    int rowc = min(row0 + rA, cnt - 1);
    const char* gAh = (const char*)(g_hhi + (size_t)(e * CAP + rowc) * DM) + q0 * 16;
    const char* gAl = (const char*)(g_hlo + (size_t)(e * CAP + rowc) * DM) + q0 * 16;
    uint32_t sA = rA * 80 + q0 * 16;

    int bk = tid >> 3, bn = (tid & 7) * 8;
    const float* pB = Wout + (size_t)e * DM * D + (size_t)bk * D + n0 + bn;
    uint32_t sB = 20480 + bk * 144 + bn * 2;

    uint32_t aB = sb + (warp_m * 64 + (lane & 15)) * 80 + (lane >> 4) * 16;
    uint32_t bB = sb + 20480 + warp_n * 4608 + (lane & 15) * 144 + ((lane >> 4) * 8) * 2;

    float acc[4][8][4];
    #pragma unroll
    for (int a = 0; a < 4; a++)
        #pragma unroll
        for (int b = 0; b < 8; b++)
            #pragma unroll
            for (int c = 0; c < 4; c++) acc[a][b][c] = 0.f;

    const int NIT = DM / 32;   // 128
    float4 vb[8];

    #define LDW_DN(IT) do { \
        const float* _w = pB + (size_t)(IT) * 32 * D; \
        vb[0] = *(const float4*)_w;         vb[1] = *(const float4*)(_w + 4); \
        vb[2] = *(const float4*)(_w + 64);  vb[3] = *(const float4*)(_w + 68); \
        vb[4] = *(const float4*)(_w + 128); vb[5] = *(const float4*)(_w + 132); \
        vb[6] = *(const float4*)(_w + 192); vb[7] = *(const float4*)(_w + 196); \
    } while (0)

    #define STW_DN(ST) do { \
        uint4 uh, ul; \
        cv8(vb[0], vb[1], uh, ul); \
        *(uint4*)(smem + (ST) + sB)           = uh; \
        *(uint4*)(smem + (ST) + sB + 18432)   = ul; \
        cv8(vb[2], vb[3], uh, ul); \
        *(uint4*)(smem + (ST) + sB + 4608)    = uh; \
        *(uint4*)(smem + (ST) + sB + 23040)   = ul; \
        cv8(vb[4], vb[5], uh, ul); \
        *(uint4*)(smem + (ST) + sB + 9216)    = uh; \
        *(uint4*)(smem + (ST) + sB + 27648)   = ul; \
        cv8(vb[6], vb[7], uh, ul); \
        *(uint4*)(smem + (ST) + sB + 13824)   = uh; \
        *(uint4*)(smem + (ST) + sB + 32256)   = ul; \
    } while (0)

    #define CPA_T(ST, IT) do { \
        uint32_t _d = sb + (ST) + sA; \
        const char* _ah = gAh + (size_t)(IT) * 64; \
        const char* _al = gAl + (size_t)(IT) * 64; \
        cpa16(_d, _ah);          cpa16(_d + 16, _ah + 16); \
        cpa16(_d + 10240, _al);  cpa16(_d + 10240 + 16, _al + 16); \
    } while (0)

    LDW_DN(0); STW_DN(0); CPA_T(0, 0); CP_COMMIT();
    LDW_DN(1);
    CP_WAIT0();
    __syncthreads();

    for (int it = 0; it < NIT; ++it) {
        uint32_t ps = (uint32_t)(it & 1) * STAGE;
        uint32_t qs = STAGE - ps;
        bool m1 = (it + 1 < NIT);
        if (m1) { STW_DN(qs); CPA_T(qs, it + 1); }
        CP_COMMIT();
        if (it + 2 < NIT) LDW_DN(it + 2);

        #pragma unroll
        for (int kk = 0; kk < 2; kk++) {
            uint32_t Ah[4][4], Al[4][4];
            #pragma unroll
            for (int f = 0; f < 4; f++) {
                ldsm4(Ah[f], aB + ps + f * 1280 + kk * 32);
                ldsm4(Al[f], aB + ps + 10240 + f * 1280 + kk * 32);
            }
            #pragma unroll
            for (int jt = 0; jt < 4; jt++) {
                uint32_t bh[4], bl[4];
                ldsm4t(bh, bB + ps + kk * 2304 + jt * 32);
                ldsm4t(bl, bB + ps + 18432 + kk * 2304 + jt * 32);
                // product-major order: same-acc reuse distance = 8 MMAs
                #pragma unroll
                for (int f = 0; f < 4; f++) {
                    mma16816(acc[f][2*jt],   Ah[f], bh[0], bh[1]);
                    mma16816(acc[f][2*jt+1], Ah[f], bh[2], bh[3]);
                }
                #pragma unroll
                for (int f = 0; f < 4; f++) {
                    mma16816(acc[f][2*jt],   Ah[f], bl[0], bl[1]);
                    mma16816(acc[f][2*jt+1], Ah[f], bl[2], bl[3]);
                }
                #pragma unroll
                for (int f = 0; f < 4; f++) {
                    mma16816(acc[f][2*jt],   Al[f], bh[0], bh[1]);
                    mma16816(acc[f][2*jt+1], Al[f], bh[2], bh[3]);
                }
            }
        }
        if (m1) CP_WAIT0();
        __syncthreads();
    }

    #pragma unroll
    for (int f = 0; f < 4; f++) {
        #pragma unroll
        for (int h = 0; h < 2; h++) {
            int r = row0 + warp_m * 64 + f * 16 + (lane >> 2) + h * 8;
            if (r >= cnt) continue;
            int   tk = g_tok[e * CAP + r];
            float wt = g_wt [e * CAP + r];
            float* po = out + (size_t)tk * D + n0 + warp_n * 64 + (lane & 3) * 2;
            #pragma unroll
            for (int n8 = 0; n8 < 8; n8++) {
                atomicAdd(po + n8 * 8,     acc[f][n8][2*h]     * wt);
                atomicAdd(po + n8 * 8 + 1, acc[f][n8][2*h + 1] * wt);
            }
        }
    }
}

// ---------------------------------------------------------------
extern "C" void kernel_launch(void* const* d_in, const int* in_sizes, int n_in,
                              void* d_out, int out_size) {
    const float* x   = (const float*)d_in[0];
    const float* Wg  = (const float*)d_in[1];
    const float* Weg = (const float*)d_in[2];
    const float* Wei = (const float*)d_in[3];
    const float* Weo = (const float*)d_in[4];
    float* out = (float*)d_out;

    static int attr_set = 0;
    if (!attr_set) {
        cudaFuncSetAttribute(moe_up_kernel, cudaFuncAttributeMaxDynamicSharedMemorySize, SMEMSZ);
        cudaFuncSetAttribute(moe_dn_kernel, cudaFuncAttributeMaxDynamicSharedMemorySize, SMEMSZ);
        attr_set = 1;
    }

    cudaMemsetAsync(out, 0, (size_t)out_size * sizeof(float));
    zero_cnt_kernel<<<1, 32>>>();
    convert_x_kernel<<<(T_TOK * D / 4) / 256, 256>>>((const float4*)x);
    router_kernel<<<T_TOK, 256>>>(x, Wg);
    moe_up_kernel<<<dim3(CAP / 128, DM / 128, E), 256, SMEMSZ>>>(Weg, Wei);
    moe_dn_kernel<<<dim3(CAP / 128, D / 256, E), 256, SMEMSZ>>>(Weo, out);
}

// round 8
// speedup vs baseline: 1.2466x; 1.0332x over previous
#include <cuda_runtime.h>
#include <cuda_bf16.h>
#include <math.h>
#include <stdint.h>

#define T_TOK 2048
#define D     1024
#define DM    4096
#define E     8
#define CAP   2048

// ---------------- device scratch (static: allocation-guard safe) ----------------
__device__ int   g_cnt[E];
__device__ int   g_tok[E * CAP];
__device__ float g_wt [E * CAP];
__device__ __nv_bfloat16 g_xhi[T_TOK * D];
__device__ __nv_bfloat16 g_xlo[T_TOK * D];
__device__ __nv_bfloat16 g_hhi[(size_t)E * CAP * DM];
__device__ __nv_bfloat16 g_hlo[(size_t)E * CAP * DM];

// ---------------- helpers ----------------
__device__ __forceinline__ uint32_t smem_u32(const void* p) {
    uint32_t a;
    asm("{ .reg .u64 t; cvta.to.shared.u64 t, %1; cvt.u32.u64 %0, t; }" : "=r"(a) : "l"(p));
    return a;
}
__device__ __forceinline__ void split2(float v, __nv_bfloat16& h, __nv_bfloat16& l) {
    h = __float2bfloat16(v);
    l = __float2bfloat16(v - __bfloat162float(h));
}
__device__ __forceinline__ uint32_t packbf(__nv_bfloat16 a, __nv_bfloat16 b) {
    __nv_bfloat162 t = __halves2bfloat162(a, b);
    return *reinterpret_cast<uint32_t*>(&t);
}
__device__ __forceinline__ void cv8(float4 a, float4 b, uint4& uh, uint4& ul) {
    __nv_bfloat16 h0, l0, h1, l1, h2, l2, h3, l3;
    split2(a.x, h0, l0); split2(a.y, h1, l1); split2(a.z, h2, l2); split2(a.w, h3, l3);
    uh.x = packbf(h0, h1); uh.y = packbf(h2, h3);
    ul.x = packbf(l0, l1); ul.y = packbf(l2, l3);
    split2(b.x, h0, l0); split2(b.y, h1, l1); split2(b.z, h2, l2); split2(b.w, h3, l3);
    uh.z = packbf(h0, h1); uh.w = packbf(h2, h3);
    ul.z = packbf(l0, l1); ul.w = packbf(l2, l3);
}
__device__ __forceinline__ void ldsm4(uint32_t (&r)[4], uint32_t addr) {
    asm volatile("ldmatrix.sync.aligned.m8n8.x4.shared.b16 {%0,%1,%2,%3}, [%4];"
        : "=r"(r[0]), "=r"(r[1]), "=r"(r[2]), "=r"(r[3]) : "r"(addr));
}
__device__ __forceinline__ void ldsm4t(uint32_t (&r)[4], uint32_t addr) {
    asm volatile("ldmatrix.sync.aligned.m8n8.x4.trans.shared.b16 {%0,%1,%2,%3}, [%4];"
        : "=r"(r[0]), "=r"(r[1]), "=r"(r[2]), "=r"(r[3]) : "r"(addr));
}
__device__ __forceinline__ void mma16816(float* d, const uint32_t (&a)[4],
                                         uint32_t b0, uint32_t b1) {
    asm volatile(
        "mma.sync.aligned.m16n8k16.row.col.f32.bf16.bf16.f32 "
        "{%0,%1,%2,%3}, {%4,%5,%6,%7}, {%8,%9}, {%0,%1,%2,%3};"
        : "+f"(d[0]), "+f"(d[1]), "+f"(d[2]), "+f"(d[3])
        : "r"(a[0]), "r"(a[1]), "r"(a[2]), "r"(a[3]), "r"(b0), "r"(b1));
}
__device__ __forceinline__ void cpa16(uint32_t s, const void* g) {
    asm volatile("cp.async.cg.shared.global [%0], [%1], 16;" :: "r"(s), "l"(g));
}
#define CP_COMMIT() asm volatile("cp.async.commit_group;" ::: "memory")
#define CP_WAIT0()  asm volatile("cp.async.wait_group 0;" ::: "memory")

// stage layout (bytes), identical to R5 (proven):
//   A hi [0,10240)  A lo [10240,20480)  B region [20480, 20480+36864)
#define STAGE   57344
#define SMEMSZ  (2 * STAGE)

// ---------------------------------------------------------------
__global__ void zero_cnt_kernel() {
    if (threadIdx.x < E) g_cnt[threadIdx.x] = 0;
}

__global__ void convert_x_kernel(const float4* __restrict__ x4) {
    int i = blockIdx.x * blockDim.x + threadIdx.x;
    float4 v = x4[i];
    __nv_bfloat16 h0, h1, h2, h3, l0, l1, l2, l3;
    split2(v.x, h0, l0); split2(v.y, h1, l1);
    split2(v.z, h2, l2); split2(v.w, h3, l3);
    ((uint2*)g_xhi)[i] = make_uint2(packbf(h0, h1), packbf(h2, h3));
    ((uint2*)g_xlo)[i] = make_uint2(packbf(l0, l1), packbf(l2, l3));
}

__global__ void router_kernel(const float* __restrict__ x,
                              const float* __restrict__ Wg) {
    int t = blockIdx.x;
    int lane = threadIdx.x & 31;
    int w = threadIdx.x >> 5;
    const float* h = x + (size_t)t * D;
    float s = 0.f;
    for (int i = lane; i < D; i += 32) s += h[i] * Wg[i * E + w];
    #pragma unroll
    for (int o = 16; o; o >>= 1) s += __shfl_xor_sync(0xffffffffu, s, o);
    __shared__ float logits[E];
    if (lane == 0) logits[w] = s;
    __syncthreads();
    if (threadIdx.x == 0) {
        float m = -1e30f;
        #pragma unroll
        for (int e = 0; e < E; e++) m = fmaxf(m, logits[e]);
        float p[E];
        #pragma unroll
        for (int e = 0; e < E; e++) p[e] = expf(logits[e] - m);
        int e0 = 0;
        #pragma unroll
        for (int e = 1; e < E; e++) if (p[e] > p[e0]) e0 = e;
        int e1 = (e0 == 0) ? 1 : 0;
        #pragma unroll
        for (int e = 0; e < E; e++) { if (e == e0) continue; if (p[e] > p[e1]) e1 = e; }
        float rs = 1.f / (p[e0] + p[e1]);
        int i0 = atomicAdd(&g_cnt[e0], 1);
        g_tok[e0 * CAP + i0] = t;  g_wt[e0 * CAP + i0] = p[e0] * rs;
        int i1 = atomicAdd(&g_cnt[e1], 1);
        g_tok[e1 * CAP + i1] = t;  g_wt[e1 * CAP + i1] = p[e1] * rs;
    }
}

// ---------------------------------------------------------------
// Up-proj: M128 x N128 (G and I each), 16 warps, warp tile m32 x n32 (both mats).
__global__ void __launch_bounds__(512, 1)
moe_up_kernel(const float* __restrict__ Wgate, const float* __restrict__ Win) {
    extern __shared__ char smem[];
    uint32_t sb = smem_u32(smem);

    int e = blockIdx.z;
    int cnt = g_cnt[e];
    int row0 = blockIdx.x * 128;
    if (row0 >= cnt) return;
    int n0 = blockIdx.y * 128;

    int tid = threadIdx.x, wid = tid >> 5, lane = tid & 31;
    int warp_m = wid >> 2, warp_n = wid & 3;   // 4 x 4

    // A loader: 512 threads = 2 splits x 128 rows x 2 chunk-pairs
    int aspl = tid >> 8;                 // 0 = hi, 1 = lo
    int rA = (tid & 255) >> 1;
    int q0 = (tid & 1) * 2;
    int tok = g_tok[e * CAP + min(row0 + rA, cnt - 1)];
    const char* gA = (const char*)((aspl ? g_xlo : g_xhi) + (size_t)tok * D) + q0 * 16;
    uint32_t sA = (uint32_t)aspl * 10240 + rA * 80 + q0 * 16;

    // B loader: bk = tid>>4 (0..31), bn = (tid&15)*8
    int bk = tid >> 4, bn = (tid & 15) * 8;
    const float* pG = Wgate + (size_t)e * D * DM + (size_t)bk * DM + n0 + bn;
    const float* pI = Win   + (size_t)e * D * DM + (size_t)bk * DM + n0 + bn;
    uint32_t sB = 20480 + (uint32_t)(bn >> 6) * 4608 + bk * 144 + (bn & 63) * 2;

    // fragment base addresses
    uint32_t aB = sb + (warp_m * 32 + (lane & 15)) * 80 + (lane >> 4) * 16;
    uint32_t bB = sb + 20480 + (warp_n >> 1) * 4608 + (lane & 15) * 144
                + ((warp_n & 1) * 32 + (lane >> 4) * 8) * 2;

    float acc[2][2][4][4];
    #pragma unroll
    for (int a = 0; a < 2; a++)
        #pragma unroll
        for (int b = 0; b < 2; b++)
            #pragma unroll
            for (int c = 0; c < 4; c++)
                #pragma unroll
                for (int d = 0; d < 4; d++) acc[a][b][c][d] = 0.f;

    const int NIT = D / 32;   // 32
    float4 vg0, vg1, vi0, vi1;

    #define LDW_UP(IT) do { \
        const float* _g = pG + (size_t)(IT) * 32 * DM; \
        const float* _i = pI + (size_t)(IT) * 32 * DM; \
        vg0 = *(const float4*)_g; vg1 = *(const float4*)(_g + 4); \
        vi0 = *(const float4*)_i; vi1 = *(const float4*)(_i + 4); \
    } while (0)

    #define STW_UP(ST) do { \
        uint4 uh, ul; \
        cv8(vg0, vg1, uh, ul); \
        *(uint4*)(smem + (ST) + sB)          = uh; \
        *(uint4*)(smem + (ST) + sB + 9216)   = ul; \
        cv8(vi0, vi1, uh, ul); \
        *(uint4*)(smem + (ST) + sB + 18432)  = uh; \
        *(uint4*)(smem + (ST) + sB + 27648)  = ul; \
    } while (0)

    #define CPA_T(ST, IT) do { \
        uint32_t _d = sb + (ST) + sA; \
        const char* _a = gA + (size_t)(IT) * 64; \
        cpa16(_d, _a);  cpa16(_d + 16, _a + 16); \
    } while (0)

    // prologue
    LDW_UP(0); STW_UP(0); CPA_T(0, 0); CP_COMMIT();
    LDW_UP(1);
    CP_WAIT0();
    __syncthreads();

    for (int it = 0; it < NIT; ++it) {
        uint32_t ps = (uint32_t)(it & 1) * STAGE;
        uint32_t qs = STAGE - ps;
        bool m1 = (it + 1 < NIT);
        if (m1) { STW_UP(qs); CPA_T(qs, it + 1); }
        CP_COMMIT();
        if (it + 2 < NIT) LDW_UP(it + 2);

        #pragma unroll
        for (int kk = 0; kk < 2; kk++) {
            uint32_t Ah[2][4], Al[2][4];
            #pragma unroll
            for (int f = 0; f < 2; f++) {
                ldsm4(Ah[f], aB + ps + f * 1280 + kk * 32);
                ldsm4(Al[f], aB + ps + 10240 + f * 1280 + kk * 32);
            }
            #pragma unroll
            for (int mat = 0; mat < 2; mat++) {
                uint32_t sec = ps + mat * 18432 + kk * 2304;
                #pragma unroll
                for (int jt = 0; jt < 2; jt++) {
                    uint32_t bh[4], bl[4];
                    ldsm4t(bh, bB + sec + jt * 32);
                    ldsm4t(bl, bB + sec + 9216 + jt * 32);
                    #pragma unroll
                    for (int f = 0; f < 2; f++) {
                        mma16816(acc[mat][f][2*jt],   Ah[f], bh[0], bh[1]);
                        mma16816(acc[mat][f][2*jt+1], Ah[f], bh[2], bh[3]);
                        mma16816(acc[mat][f][2*jt],   Ah[f], bl[0], bl[1]);
                        mma16816(acc[mat][f][2*jt+1], Ah[f], bl[2], bl[3]);
                        mma16816(acc[mat][f][2*jt],   Al[f], bh[0], bh[1]);
                        mma16816(acc[mat][f][2*jt+1], Al[f], bh[2], bh[3]);
                    }
                }
            }
        }
        if (m1) CP_WAIT0();
        __syncthreads();
    }

    // epilogue: silu(G)*I -> split bf16 -> g_hhi/g_hlo
    #pragma unroll
    for (int f = 0; f < 2; f++) {
        #pragma unroll
        for (int h = 0; h < 2; h++) {
            int r = row0 + warp_m * 32 + f * 16 + (lane >> 2) + h * 8;
            if (r >= cnt) continue;
            size_t base = (size_t)(e * CAP + r) * DM;
            int col = n0 + warp_n * 32 + (lane & 3) * 2;
            #pragma unroll
            for (int n8 = 0; n8 < 4; n8++) {
                float g0 = acc[0][f][n8][2*h], g1 = acc[0][f][n8][2*h+1];
                float i0 = acc[1][f][n8][2*h], i1 = acc[1][f][n8][2*h+1];
                float v0 = g0 / (1.f + __expf(-g0)) * i0;
                float v1 = g1 / (1.f + __expf(-g1)) * i1;
                __nv_bfloat16 h0, l0, h1, l1;
                split2(v0, h0, l0); split2(v1, h1, l1);
                *(uint32_t*)(g_hhi + base + col + n8 * 8) = packbf(h0, h1);
                *(uint32_t*)(g_hlo + base + col + n8 * 8) = packbf(l0, l1);
            }
        }
    }
    #undef LDW_UP
    #undef STW_UP
    #undef CPA_T
}

// ---------------------------------------------------------------
// Down-proj + scatter: M128 x N256 tile, 16 warps, warp tile m32 x n64.
__global__ void __launch_bounds__(512, 1)
moe_dn_kernel(const float* __restrict__ Wout, float* __restrict__ out) {
    extern __shared__ char smem[];
    uint32_t sb = smem_u32(smem);

    int e = blockIdx.z;
    int cnt = g_cnt[e];
    int row0 = blockIdx.x * 128;
    if (row0 >= cnt) return;
    int n0 = blockIdx.y * 256;

    int tid = threadIdx.x, wid = tid >> 5, lane = tid & 31;
    int warp_m = wid >> 2, warp_n = wid & 3;

    int aspl = tid >> 8;
    int rA = (tid & 255) >> 1;
    int q0 = (tid & 1) * 2;
    int rowc = min(row0 + rA, cnt - 1);
    const char* gA = (const char*)((aspl ? g_hlo : g_hhi) + (size_t)(e * CAP + rowc) * DM) + q0 * 16;
    uint32_t sA = (uint32_t)aspl * 10240 + rA * 80 + q0 * 16;

    // B loader: bk = tid>>4 (0..31), bn = (tid&15)*16 (16 floats)
    int bk = tid >> 4, bn = (tid & 15) * 16;
    const float* pB = Wout + (size_t)e * DM * D + (size_t)bk * D + n0 + bn;
    uint32_t sB = 20480 + (uint32_t)(bn >> 6) * 4608 + bk * 144 + (bn & 63) * 2;

    uint32_t aB = sb + (warp_m * 32 + (lane & 15)) * 80 + (lane >> 4) * 16;
    uint32_t bB = sb + 20480 + warp_n * 4608 + (lane & 15) * 144 + (lane >> 4) * 16;

    float acc[2][8][4];
    #pragma unroll
    for (int a = 0; a < 2; a++)
        #pragma unroll
        for (int b = 0; b < 8; b++)
            #pragma unroll
            for (int c = 0; c < 4; c++) acc[a][b][c] = 0.f;

    const int NIT = DM / 32;   // 128
    float4 vb0, vb1, vb2, vb3;

    #define LDW_DN(IT) do { \
        const float* _w = pB + (size_t)(IT) * 32 * D; \
        vb0 = *(const float4*)_w;      vb1 = *(const float4*)(_w + 4); \
        vb2 = *(const float4*)(_w + 8); vb3 = *(const float4*)(_w + 12); \
    } while (0)

    #define STW_DN(ST) do { \
        uint4 uh, ul; \
        cv8(vb0, vb1, uh, ul); \
        *(uint4*)(smem + (ST) + sB)           = uh; \
        *(uint4*)(smem + (ST) + sB + 18432)   = ul; \
        cv8(vb2, vb3, uh, ul); \
        *(uint4*)(smem + (ST) + sB + 16)      = uh; \
        *(uint4*)(smem + (ST) + sB + 18448)   = ul; \
    } while (0)

    #define CPA_T(ST, IT) do { \
        uint32_t _d = sb + (ST) + sA; \
        const char* _a = gA + (size_t)(IT) * 64; \
        cpa16(_d, _a);  cpa16(_d + 16, _a + 16); \
    } while (0)

    LDW_DN(0); STW_DN(0); CPA_T(0, 0); CP_COMMIT();
    LDW_DN(1);
    CP_WAIT0();
    __syncthreads();

    for (int it = 0; it < NIT; ++it) {
        uint32_t ps = (uint32_t)(it & 1) * STAGE;
        uint32_t qs = STAGE - ps;
        bool m1 = (it + 1 < NIT);
        if (m1) { STW_DN(qs); CPA_T(qs, it + 1); }
        CP_COMMIT();
        if (it + 2 < NIT) LDW_DN(it + 2);

        #pragma unroll
        for (int kk = 0; kk < 2; kk++) {
            uint32_t Ah[2][4], Al[2][4];
            #pragma unroll
            for (int f = 0; f < 2; f++) {
                ldsm4(Ah[f], aB + ps + f * 1280 + kk * 32);
                ldsm4(Al[f], aB + ps + 10240 + f * 1280 + kk * 32);
            }
            #pragma unroll
            for (int jt = 0; jt < 4; jt++) {
                uint32_t bh[4], bl[4];
                ldsm4t(bh, bB + ps + kk * 2304 + jt * 32);
                ldsm4t(bl, bB + ps + 18432 + kk * 2304 + jt * 32);
                #pragma unroll
                for (int f = 0; f < 2; f++) {
                    mma16816(acc[f][2*jt],   Ah[f], bh[0], bh[1]);
                    mma16816(acc[f][2*jt+1], Ah[f], bh[2], bh[3]);
                    mma16816(acc[f][2*jt],   Ah[f], bl[0], bl[1]);
                    mma16816(acc[f][2*jt+1], Ah[f], bl[2], bl[3]);
                    mma16816(acc[f][2*jt],   Al[f], bh[0], bh[1]);
                    mma16816(acc[f][2*jt+1], Al[f], bh[2], bh[3]);
                }
            }
        }
        if (m1) CP_WAIT0();
        __syncthreads();
    }

    #pragma unroll
    for (int f = 0; f < 2; f++) {
        #pragma unroll
        for (int h = 0; h < 2; h++) {
            int r = row0 + warp_m * 32 + f * 16 + (lane >> 2) + h * 8;
            if (r >= cnt) continue;
            int   tk = g_tok[e * CAP + r];
            float wt = g_wt [e * CAP + r];
            float* po = out + (size_t)tk * D + n0 + warp_n * 64 + (lane & 3) * 2;
            #pragma unroll
            for (int n8 = 0; n8 < 8; n8++) {
                atomicAdd(po + n8 * 8,     acc[f][n8][2*h]     * wt);
                atomicAdd(po + n8 * 8 + 1, acc[f][n8][2*h + 1] * wt);
            }
        }
    }
    #undef LDW_DN
    #undef STW_DN
    #undef CPA_T
}

// ---------------------------------------------------------------
extern "C" void kernel_launch(void* const* d_in, const int* in_sizes, int n_in,
                              void* d_out, int out_size) {
    const float* x   = (const float*)d_in[0];
    const float* Wg  = (const float*)d_in[1];
    const float* Weg = (const float*)d_in[2];
    const float* Wei = (const float*)d_in[3];
    const float* Weo = (const float*)d_in[4];
    float* out = (float*)d_out;

    static int attr_set = 0;
    if (!attr_set) {
        cudaFuncSetAttribute(moe_up_kernel, cudaFuncAttributeMaxDynamicSharedMemorySize, SMEMSZ);
        cudaFuncSetAttribute(moe_dn_kernel, cudaFuncAttributeMaxDynamicSharedMemorySize, SMEMSZ);
        attr_set = 1;
    }

    cudaMemsetAsync(out, 0, (size_t)out_size * sizeof(float));
    zero_cnt_kernel<<<1, 32>>>();
    convert_x_kernel<<<(T_TOK * D / 4) / 256, 256>>>((const float4*)x);
    router_kernel<<<T_TOK, 256>>>(x, Wg);
    moe_up_kernel<<<dim3(CAP / 128, DM / 128, E), 512, SMEMSZ>>>(Weg, Wei);
    moe_dn_kernel<<<dim3(CAP / 128, D / 256, E), 512, SMEMSZ>>>(Weo, out);
}

// round 9
// speedup vs baseline: 2.2905x; 1.8374x over previous
#include <cuda_runtime.h>
#include <cuda_fp16.h>
#include <math.h>
#include <stdint.h>

#define T_TOK 2048
#define D     1024
#define DM    4096
#define E     8
#define CAP   2048

// ---------------- device scratch (static: allocation-guard safe) ----------------
__device__ int   g_cnt[E];
__device__ int   g_tok[E * CAP];
__device__ float g_wt [E * CAP];
__device__ __half g_xh[T_TOK * D];
__device__ __half g_hh[(size_t)E * CAP * DM];   // 128 MB

// ---------------- helpers ----------------
__device__ __forceinline__ uint32_t smem_u32(const void* p) {
    uint32_t a;
    asm("{ .reg .u64 t; cvta.to.shared.u64 t, %1; cvt.u32.u64 %0, t; }" : "=r"(a) : "l"(p));
    return a;
}
__device__ __forceinline__ uint32_t packh(float a, float b) {
    __half2 t = __floats2half2_rn(a, b);
    return *reinterpret_cast<uint32_t*>(&t);
}
__device__ __forceinline__ void cv8h(float4 a, float4 b, uint4& u) {
    u.x = packh(a.x, a.y); u.y = packh(a.z, a.w);
    u.z = packh(b.x, b.y); u.w = packh(b.z, b.w);
}
__device__ __forceinline__ void ldsm4(uint32_t (&r)[4], uint32_t addr) {
    asm volatile("ldmatrix.sync.aligned.m8n8.x4.shared.b16 {%0,%1,%2,%3}, [%4];"
        : "=r"(r[0]), "=r"(r[1]), "=r"(r[2]), "=r"(r[3]) : "r"(addr));
}
__device__ __forceinline__ void ldsm4t(uint32_t (&r)[4], uint32_t addr) {
    asm volatile("ldmatrix.sync.aligned.m8n8.x4.trans.shared.b16 {%0,%1,%2,%3}, [%4];"
        : "=r"(r[0]), "=r"(r[1]), "=r"(r[2]), "=r"(r[3]) : "r"(addr));
}
__device__ __forceinline__ void mma16816(float* d, const uint32_t (&a)[4],
                                         uint32_t b0, uint32_t b1) {
    asm volatile(
        "mma.sync.aligned.m16n8k16.row.col.f32.f16.f16.f32 "
        "{%0,%1,%2,%3}, {%4,%5,%6,%7}, {%8,%9}, {%0,%1,%2,%3};"
        : "+f"(d[0]), "+f"(d[1]), "+f"(d[2]), "+f"(d[3])
        : "r"(a[0]), "r"(a[1]), "r"(a[2]), "r"(a[3]), "r"(b0), "r"(b1));
}
__device__ __forceinline__ void cpa16(uint32_t s, const void* g) {
    asm volatile("cp.async.cg.shared.global [%0], [%1], 16;" :: "r"(s), "l"(g));
}
#define CP_COMMIT() asm volatile("cp.async.commit_group;" ::: "memory")
#define CP_WAIT0()  asm volatile("cp.async.wait_group 0;" ::: "memory")

// stage layout (bytes):
//   A [0,10240): 128 rows x 80B (64B data + 16 pad)
//   B [10240, 10240+18432): 4 blocks x (32 k-rows x 144B) = 4x4608
#define STAGE   28672
#define SMEMSZ  (2 * STAGE)

// ---------------------------------------------------------------
__global__ void zero_cnt_kernel() {
    if (threadIdx.x < E) g_cnt[threadIdx.x] = 0;
}

__global__ void convert_x_kernel(const float4* __restrict__ x4) {
    int i = blockIdx.x * blockDim.x + threadIdx.x;
    float4 v = x4[i];
    ((uint2*)g_xh)[i] = make_uint2(packh(v.x, v.y), packh(v.z, v.w));
}

__global__ void router_kernel(const float* __restrict__ x,
                              const float* __restrict__ Wg) {
    int t = blockIdx.x;
    int lane = threadIdx.x & 31;
    int w = threadIdx.x >> 5;
    const float* h = x + (size_t)t * D;
    float s = 0.f;
    for (int i = lane; i < D; i += 32) s += h[i] * Wg[i * E + w];
    #pragma unroll
    for (int o = 16; o; o >>= 1) s += __shfl_xor_sync(0xffffffffu, s, o);
    __shared__ float logits[E];
    if (lane == 0) logits[w] = s;
    __syncthreads();
    if (threadIdx.x == 0) {
        float m = -1e30f;
        #pragma unroll
        for (int e = 0; e < E; e++) m = fmaxf(m, logits[e]);
        float p[E];
        #pragma unroll
        for (int e = 0; e < E; e++) p[e] = expf(logits[e] - m);
        int e0 = 0;
        #pragma unroll
        for (int e = 1; e < E; e++) if (p[e] > p[e0]) e0 = e;
        int e1 = (e0 == 0) ? 1 : 0;
        #pragma unroll
        for (int e = 0; e < E; e++) { if (e == e0) continue; if (p[e] > p[e1]) e1 = e; }
        float rs = 1.f / (p[e0] + p[e1]);
        int i0 = atomicAdd(&g_cnt[e0], 1);
        g_tok[e0 * CAP + i0] = t;  g_wt[e0 * CAP + i0] = p[e0] * rs;
        int i1 = atomicAdd(&g_cnt[e1], 1);
        g_tok[e1 * CAP + i1] = t;  g_wt[e1 * CAP + i1] = p[e1] * rs;
    }
}

// ---------------------------------------------------------------
// Up-proj: M128 x N128 (G and I each), 16 warps, warp tile m32 x n32 (both mats).
// fp16 single-product, fp32 accumulate.
__global__ void __launch_bounds__(512, 1)
moe_up_kernel(const float* __restrict__ Wgate, const float* __restrict__ Win) {
    extern __shared__ char smem[];
    uint32_t sb = smem_u32(smem);

    int e = blockIdx.z;
    int cnt = g_cnt[e];
    int row0 = blockIdx.x * 128;
    if (row0 >= cnt) return;
    int n0 = blockIdx.y * 128;

    int tid = threadIdx.x, wid = tid >> 5, lane = tid & 31;
    int warp_m = wid >> 2, warp_n = wid & 3;   // 4 x 4

    // A loader: 512 threads = 128 rows x 4 chunks(16B)
    int rA = tid >> 2, q = tid & 3;
    int tok = g_tok[e * CAP + min(row0 + rA, cnt - 1)];
    const char* gA = (const char*)(g_xh + (size_t)tok * D) + q * 16;
    uint32_t sA = rA * 80 + q * 16;

    // B loader: bk = tid>>4 (0..31), bn = (tid&15)*8
    int bk = tid >> 4, bn = (tid & 15) * 8;
    const float* pG = Wgate + (size_t)e * D * DM + (size_t)bk * DM + n0 + bn;
    const float* pI = Win   + (size_t)e * D * DM + (size_t)bk * DM + n0 + bn;
    uint32_t sB = 10240 + (uint32_t)(bn >> 6) * 4608 + bk * 144 + (bn & 63) * 2;

    // fragment base addresses
    uint32_t aB = sb + (warp_m * 32 + (lane & 15)) * 80 + (lane >> 4) * 16;
    uint32_t bB = sb + 10240 + (warp_n >> 1) * 4608 + (lane & 15) * 144
                + ((warp_n & 1) * 32 + (lane >> 4) * 8) * 2;

    float acc[2][2][4][4];
    #pragma unroll
    for (int a = 0; a < 2; a++)
        #pragma unroll
        for (int b = 0; b < 2; b++)
            #pragma unroll
            for (int c = 0; c < 4; c++)
                #pragma unroll
                for (int d = 0; d < 4; d++) acc[a][b][c][d] = 0.f;

    const int NIT = D / 32;   // 32
    float4 vg0, vg1, vi0, vi1;

    #define LDW_UP(IT) do { \
        const float* _g = pG + (size_t)(IT) * 32 * DM; \
        const float* _i = pI + (size_t)(IT) * 32 * DM; \
        vg0 = *(const float4*)_g; vg1 = *(const float4*)(_g + 4); \
        vi0 = *(const float4*)_i; vi1 = *(const float4*)(_i + 4); \
    } while (0)

    #define STW_UP(ST) do { \
        uint4 u; \
        cv8h(vg0, vg1, u); \
        *(uint4*)(smem + (ST) + sB)          = u; \
        cv8h(vi0, vi1, u); \
        *(uint4*)(smem + (ST) + sB + 9216)   = u; \
    } while (0)

    #define CPA_T(ST, IT) do { \
        cpa16(sb + (ST) + sA, gA + (size_t)(IT) * 64); \
    } while (0)

    // prologue
    LDW_UP(0); STW_UP(0); CPA_T(0, 0); CP_COMMIT();
    LDW_UP(1);
    CP_WAIT0();
    __syncthreads();

    for (int it = 0; it < NIT; ++it) {
        uint32_t ps = (uint32_t)(it & 1) * STAGE;
        uint32_t qs = STAGE - ps;
        bool m1 = (it + 1 < NIT);
        if (m1) { STW_UP(qs); CPA_T(qs, it + 1); }
        CP_COMMIT();
        if (it + 2 < NIT) LDW_UP(it + 2);

        #pragma unroll
        for (int kk = 0; kk < 2; kk++) {
            uint32_t A[2][4];
            #pragma unroll
            for (int f = 0; f < 2; f++)
                ldsm4(A[f], aB + ps + f * 1280 + kk * 32);
            #pragma unroll
            for (int mat = 0; mat < 2; mat++) {
                uint32_t sec = ps + mat * 9216 + kk * 2304;
                #pragma unroll
                for (int jt = 0; jt < 2; jt++) {
                    uint32_t bh[4];
                    ldsm4t(bh, bB + sec + jt * 32);
                    #pragma unroll
                    for (int f = 0; f < 2; f++) {
                        mma16816(acc[mat][f][2*jt],   A[f], bh[0], bh[1]);
                        mma16816(acc[mat][f][2*jt+1], A[f], bh[2], bh[3]);
                    }
                }
            }
        }
        if (m1) CP_WAIT0();
        __syncthreads();
    }

    // epilogue: silu(G)*I -> fp16 -> g_hh
    #pragma unroll
    for (int f = 0; f < 2; f++) {
        #pragma unroll
        for (int h = 0; h < 2; h++) {
            int r = row0 + warp_m * 32 + f * 16 + (lane >> 2) + h * 8;
            if (r >= cnt) continue;
            size_t base = (size_t)(e * CAP + r) * DM;
            int col = n0 + warp_n * 32 + (lane & 3) * 2;
            #pragma unroll
            for (int n8 = 0; n8 < 4; n8++) {
                float g0 = acc[0][f][n8][2*h], g1 = acc[0][f][n8][2*h+1];
                float i0 = acc[1][f][n8][2*h], i1 = acc[1][f][n8][2*h+1];
                float v0 = g0 / (1.f + __expf(-g0)) * i0;
                float v1 = g1 / (1.f + __expf(-g1)) * i1;
                *(uint32_t*)(g_hh + base + col + n8 * 8) = packh(v0, v1);
            }
        }
    }
    #undef LDW_UP
    #undef STW_UP
    #undef CPA_T
}

// ---------------------------------------------------------------
// Down-proj + scatter: M128 x N256 tile, 16 warps, warp tile m32 x n64.
__global__ void __launch_bounds__(512, 1)
moe_dn_kernel(const float* __restrict__ Wout, float* __restrict__ out) {
    extern __shared__ char smem[];
    uint32_t sb = smem_u32(smem);

    int e = blockIdx.z;
    int cnt = g_cnt[e];
    int row0 = blockIdx.x * 128;
    if (row0 >= cnt) return;
    int n0 = blockIdx.y * 256;

    int tid = threadIdx.x, wid = tid >> 5, lane = tid & 31;
    int warp_m = wid >> 2, warp_n = wid & 3;

    int rA = tid >> 2, q = tid & 3;
    int rowc = min(row0 + rA, cnt - 1);
    const char* gA = (const char*)(g_hh + (size_t)(e * CAP + rowc) * DM) + q * 16;
    uint32_t sA = rA * 80 + q * 16;

    // B loader: bk = tid>>4 (0..31), bn = (tid&15)*16
    int bk = tid >> 4, bn = (tid & 15) * 16;
    const float* pB = Wout + (size_t)e * DM * D + (size_t)bk * D + n0 + bn;
    uint32_t sB = 10240 + (uint32_t)(bn >> 6) * 4608 + bk * 144 + (bn & 63) * 2;

    uint32_t aB = sb + (warp_m * 32 + (lane & 15)) * 80 + (lane >> 4) * 16;
    uint32_t bB = sb + 10240 + warp_n * 4608 + (lane & 15) * 144 + (lane >> 4) * 16;

    float acc[2][8][4];
    #pragma unroll
    for (int a = 0; a < 2; a++)
        #pragma unroll
        for (int b = 0; b < 8; b++)
            #pragma unroll
            for (int c = 0; c < 4; c++) acc[a][b][c] = 0.f;

    const int NIT = DM / 32;   // 128
    float4 vb0, vb1, vb2, vb3;

    #define LDW_DN(IT) do { \
        const float* _w = pB + (size_t)(IT) * 32 * D; \
        vb0 = *(const float4*)_w;       vb1 = *(const float4*)(_w + 4); \
        vb2 = *(const float4*)(_w + 8); vb3 = *(const float4*)(_w + 12); \
    } while (0)

    #define STW_DN(ST) do { \
        uint4 u; \
        cv8h(vb0, vb1, u); \
        *(uint4*)(smem + (ST) + sB)       = u; \
        cv8h(vb2, vb3, u); \
        *(uint4*)(smem + (ST) + sB + 16)  = u; \
    } while (0)

    #define CPA_T(ST, IT) do { \
        cpa16(sb + (ST) + sA, gA + (size_t)(IT) * 64); \
    } while (0)

    LDW_DN(0); STW_DN(0); CPA_T(0, 0); CP_COMMIT();
    LDW_DN(1);
    CP_WAIT0();
    __syncthreads();

    for (int it = 0; it < NIT; ++it) {
        uint32_t ps = (uint32_t)(it & 1) * STAGE;
        uint32_t qs = STAGE - ps;
        bool m1 = (it + 1 < NIT);
        if (m1) { STW_DN(qs); CPA_T(qs, it + 1); }
        CP_COMMIT();
        if (it + 2 < NIT) LDW_DN(it + 2);

        #pragma unroll
        for (int kk = 0; kk < 2; kk++) {
            uint32_t A[2][4];
            #pragma unroll
            for (int f = 0; f < 2; f++)
                ldsm4(A[f], aB + ps + f * 1280 + kk * 32);
            #pragma unroll
            for (int jt = 0; jt < 4; jt++) {
                uint32_t bh[4];
                ldsm4t(bh, bB + ps + kk * 2304 + jt * 32);
                #pragma unroll
                for (int f = 0; f < 2; f++) {
                    mma16816(acc[f][2*jt],   A[f], bh[0], bh[1]);
                    mma16816(acc[f][2*jt+1], A[f], bh[2], bh[3]);
                }
            }
        }
        if (m1) CP_WAIT0();
        __syncthreads();
    }

    #pragma unroll
    for (int f = 0; f < 2; f++) {
        #pragma unroll
        for (int h = 0; h < 2; h++) {
            int r = row0 + warp_m * 32 + f * 16 + (lane >> 2) + h * 8;
            if (r >= cnt) continue;
            int   tk = g_tok[e * CAP + r];
            float wt = g_wt [e * CAP + r];
            float* po = out + (size_t)tk * D + n0 + warp_n * 64 + (lane & 3) * 2;
            #pragma unroll
            for (int n8 = 0; n8 < 8; n8++) {
                atomicAdd(po + n8 * 8,     acc[f][n8][2*h]     * wt);
                atomicAdd(po + n8 * 8 + 1, acc[f][n8][2*h + 1] * wt);
            }
        }
    }
    #undef LDW_DN
    #undef STW_DN
    #undef CPA_T
}

// ---------------------------------------------------------------
extern "C" void kernel_launch(void* const* d_in, const int* in_sizes, int n_in,
                              void* d_out, int out_size) {
    const float* x   = (const float*)d_in[0];
    const float* Wg  = (const float*)d_in[1];
    const float* Weg = (const float*)d_in[2];
    const float* Wei = (const float*)d_in[3];
    const float* Weo = (const float*)d_in[4];
    float* out = (float*)d_out;

    static int attr_set = 0;
    if (!attr_set) {
        cudaFuncSetAttribute(moe_up_kernel, cudaFuncAttributeMaxDynamicSharedMemorySize, SMEMSZ);
        cudaFuncSetAttribute(moe_dn_kernel, cudaFuncAttributeMaxDynamicSharedMemorySize, SMEMSZ);
        attr_set = 1;
    }

    cudaMemsetAsync(out, 0, (size_t)out_size * sizeof(float));
    zero_cnt_kernel<<<1, 32>>>();
    convert_x_kernel<<<(T_TOK * D / 4) / 256, 256>>>((const float4*)x);
    router_kernel<<<T_TOK, 256>>>(x, Wg);
    moe_up_kernel<<<dim3(CAP / 128, DM / 128, E), 512, SMEMSZ>>>(Weg, Wei);
    moe_dn_kernel<<<dim3(CAP / 128, D / 256, E), 512, SMEMSZ>>>(Weo, out);
}

// round 10
// speedup vs baseline: 2.3993x; 1.0475x over previous
#include <cuda_runtime.h>
#include <cuda_fp16.h>
#include <math.h>
#include <stdint.h>

#define T_TOK 2048
#define D     1024
#define DM    4096
#define E     8
#define CAP   2048

// ---------------- device scratch (static: allocation-guard safe) ----------------
__device__ int   g_cnt[E];
__device__ int   g_tok[E * CAP];
__device__ float g_wt [E * CAP];
__device__ __half g_xh[T_TOK * D];
__device__ __half g_hh[(size_t)E * CAP * DM];   // 128 MB

// ---------------- helpers ----------------
__device__ __forceinline__ uint32_t smem_u32(const void* p) {
    uint32_t a;
    asm("{ .reg .u64 t; cvta.to.shared.u64 t, %1; cvt.u32.u64 %0, t; }" : "=r"(a) : "l"(p));
    return a;
}
__device__ __forceinline__ uint32_t packh(float a, float b) {
    __half2 t = __floats2half2_rn(a, b);
    return *reinterpret_cast<uint32_t*>(&t);
}
__device__ __forceinline__ void cv8h(float4 a, float4 b, uint4& u) {
    u.x = packh(a.x, a.y); u.y = packh(a.z, a.w);
    u.z = packh(b.x, b.y); u.w = packh(b.z, b.w);
}
__device__ __forceinline__ float4 ldg_cg4(const float* p) {
    float4 v;
    asm volatile("ld.global.cg.v4.f32 {%0,%1,%2,%3}, [%4];"
        : "=f"(v.x), "=f"(v.y), "=f"(v.z), "=f"(v.w) : "l"(p));
    return v;
}
__device__ __forceinline__ void ldsm4(uint32_t (&r)[4], uint32_t addr) {
    asm volatile("ldmatrix.sync.aligned.m8n8.x4.shared.b16 {%0,%1,%2,%3}, [%4];"
        : "=r"(r[0]), "=r"(r[1]), "=r"(r[2]), "=r"(r[3]) : "r"(addr));
}
__device__ __forceinline__ void ldsm4t(uint32_t (&r)[4], uint32_t addr) {
    asm volatile("ldmatrix.sync.aligned.m8n8.x4.trans.shared.b16 {%0,%1,%2,%3}, [%4];"
        : "=r"(r[0]), "=r"(r[1]), "=r"(r[2]), "=r"(r[3]) : "r"(addr));
}
__device__ __forceinline__ void mma16816(float* d, const uint32_t (&a)[4],
                                         uint32_t b0, uint32_t b1) {
    asm volatile(
        "mma.sync.aligned.m16n8k16.row.col.f32.f16.f16.f32 "
        "{%0,%1,%2,%3}, {%4,%5,%6,%7}, {%8,%9}, {%0,%1,%2,%3};"
        : "+f"(d[0]), "+f"(d[1]), "+f"(d[2]), "+f"(d[3])
        : "r"(a[0]), "r"(a[1]), "r"(a[2]), "r"(a[3]), "r"(b0), "r"(b1));
}
__device__ __forceinline__ void cpa16(uint32_t s, const void* g) {
    asm volatile("cp.async.cg.shared.global [%0], [%1], 16;" :: "r"(s), "l"(g));
}
#define CP_COMMIT() asm volatile("cp.async.commit_group;" ::: "memory")
#define CP_WAIT0()  asm volatile("cp.async.wait_group 0;" ::: "memory")

// stage layout (bytes), BK=64:
//   A [0,18432): 128 rows x 144B (128B data + 16 pad)
//   B [18432, 18432+36864): 4 blocks x (64 k-rows x 144B) = 4 x 9216
#define STAGE   55296
#define SMEMSZ  (2 * STAGE)

// ---------------------------------------------------------------
__global__ void zero_cnt_kernel() {
    if (threadIdx.x < E) g_cnt[threadIdx.x] = 0;
}

__global__ void convert_x_kernel(const float4* __restrict__ x4) {
    int i = blockIdx.x * blockDim.x + threadIdx.x;
    float4 v = x4[i];
    ((uint2*)g_xh)[i] = make_uint2(packh(v.x, v.y), packh(v.z, v.w));
}

__global__ void router_kernel(const float* __restrict__ x,
                              const float* __restrict__ Wg) {
    int t = blockIdx.x;
    int lane = threadIdx.x & 31;
    int w = threadIdx.x >> 5;
    const float* h = x + (size_t)t * D;
    float s = 0.f;
    for (int i = lane; i < D; i += 32) s += h[i] * Wg[i * E + w];
    #pragma unroll
    for (int o = 16; o; o >>= 1) s += __shfl_xor_sync(0xffffffffu, s, o);
    __shared__ float logits[E];
    if (lane == 0) logits[w] = s;
    __syncthreads();
    if (threadIdx.x == 0) {
        float m = -1e30f;
        #pragma unroll
        for (int e = 0; e < E; e++) m = fmaxf(m, logits[e]);
        float p[E];
        #pragma unroll
        for (int e = 0; e < E; e++) p[e] = expf(logits[e] - m);
        int e0 = 0;
        #pragma unroll
        for (int e = 1; e < E; e++) if (p[e] > p[e0]) e0 = e;
        int e1 = (e0 == 0) ? 1 : 0;
        #pragma unroll
        for (int e = 0; e < E; e++) { if (e == e0) continue; if (p[e] > p[e1]) e1 = e; }
        float rs = 1.f / (p[e0] + p[e1]);
        int i0 = atomicAdd(&g_cnt[e0], 1);
        g_tok[e0 * CAP + i0] = t;  g_wt[e0 * CAP + i0] = p[e0] * rs;
        int i1 = atomicAdd(&g_cnt[e1], 1);
        g_tok[e1 * CAP + i1] = t;  g_wt[e1 * CAP + i1] = p[e1] * rs;
    }
}

// ---------------------------------------------------------------
// Up-proj: M128 x N128 (G and I each), 16 warps, warp tile m32 x n32 (both mats).
// fp16 single-product, fp32 accumulate, BK=64. wt folded into hid output.
__global__ void __launch_bounds__(512, 1)
moe_up_kernel(const float* __restrict__ Wgate, const float* __restrict__ Win) {
    extern __shared__ char smem[];
    uint32_t sb = smem_u32(smem);

    int e = blockIdx.z;
    int cnt = g_cnt[e];
    int row0 = blockIdx.x * 128;
    if (row0 >= cnt) return;
    int n0 = blockIdx.y * 128;

    int tid = threadIdx.x, wid = tid >> 5, lane = tid & 31;
    int warp_m = wid >> 2, warp_n = wid & 3;   // 4 x 4

    // A loader: 512 threads = 128 rows x 4 chunks(32B)
    int rA = tid >> 2, q = tid & 3;
    int tok = g_tok[e * CAP + min(row0 + rA, cnt - 1)];
    const char* gA = (const char*)(g_xh + (size_t)tok * D) + q * 32;
    uint32_t sA = rA * 144 + q * 32;

    // B loader: bk = tid>>4 (0..31), bn = (tid&15)*8; k's bk and bk+32
    int bk = tid >> 4, bn = (tid & 15) * 8;
    const float* pG = Wgate + (size_t)e * D * DM + (size_t)bk * DM + n0 + bn;
    const float* pI = Win   + (size_t)e * D * DM + (size_t)bk * DM + n0 + bn;
    uint32_t sB = 18432 + (uint32_t)(bn >> 6) * 9216 + bk * 144 + (bn & 63) * 2;

    // fragment base addresses
    uint32_t aB = sb + (warp_m * 32 + (lane & 15)) * 144 + (lane >> 4) * 16;
    uint32_t bB = sb + 18432 + (warp_n >> 1) * 9216 + (lane & 15) * 144
                + ((warp_n & 1) * 32 + (lane >> 4) * 8) * 2;

    float acc[2][2][4][4];
    #pragma unroll
    for (int a = 0; a < 2; a++)
        #pragma unroll
        for (int b = 0; b < 2; b++)
            #pragma unroll
            for (int c = 0; c < 4; c++)
                #pragma unroll
                for (int d = 0; d < 4; d++) acc[a][b][c][d] = 0.f;

    const int NIT = D / 64;   // 16
    float4 vg[4], vi[4];

    #define LDW_UP(IT) do { \
        const float* _g = pG + (size_t)(IT) * 64 * DM; \
        const float* _i = pI + (size_t)(IT) * 64 * DM; \
        vg[0] = ldg_cg4(_g);            vg[1] = ldg_cg4(_g + 4); \
        vg[2] = ldg_cg4(_g + 32 * DM);  vg[3] = ldg_cg4(_g + 32 * DM + 4); \
        vi[0] = ldg_cg4(_i);            vi[1] = ldg_cg4(_i + 4); \
        vi[2] = ldg_cg4(_i + 32 * DM);  vi[3] = ldg_cg4(_i + 32 * DM + 4); \
    } while (0)

    #define STW_UP(ST) do { \
        uint4 u; \
        cv8h(vg[0], vg[1], u);  *(uint4*)(smem + (ST) + sB)                 = u; \
        cv8h(vg[2], vg[3], u);  *(uint4*)(smem + (ST) + sB + 4608)          = u; \
        cv8h(vi[0], vi[1], u);  *(uint4*)(smem + (ST) + sB + 18432)         = u; \
        cv8h(vi[2], vi[3], u);  *(uint4*)(smem + (ST) + sB + 18432 + 4608)  = u; \
    } while (0)

    #define CPA_T(ST, IT) do { \
        const char* _a = gA + (size_t)(IT) * 128; \
        cpa16(sb + (ST) + sA, _a); \
        cpa16(sb + (ST) + sA + 16, _a + 16); \
    } while (0)

    // prologue
    LDW_UP(0); STW_UP(0); CPA_T(0, 0); CP_COMMIT();
    LDW_UP(1);
    CP_WAIT0();
    __syncthreads();

    for (int it = 0; it < NIT; ++it) {
        uint32_t ps = (uint32_t)(it & 1) * STAGE;
        uint32_t qs = STAGE - ps;
        bool m1 = (it + 1 < NIT);
        if (m1) { STW_UP(qs); CPA_T(qs, it + 1); }
        CP_COMMIT();
        if (it + 2 < NIT) LDW_UP(it + 2);

        #pragma unroll
        for (int kk = 0; kk < 4; kk++) {
            uint32_t A[2][4];
            #pragma unroll
            for (int f = 0; f < 2; f++)
                ldsm4(A[f], aB + ps + f * 2304 + kk * 32);
            #pragma unroll
            for (int mat = 0; mat < 2; mat++) {
                uint32_t sec = ps + mat * 18432 + kk * 2304;
                #pragma unroll
                for (int jt = 0; jt < 2; jt++) {
                    uint32_t bh[4];
                    ldsm4t(bh, bB + sec + jt * 32);
                    #pragma unroll
                    for (int f = 0; f < 2; f++) {
                        mma16816(acc[mat][f][2*jt],   A[f], bh[0], bh[1]);
                        mma16816(acc[mat][f][2*jt+1], A[f], bh[2], bh[3]);
                    }
                }
            }
        }
        if (m1) CP_WAIT0();
        __syncthreads();
    }

    // epilogue: wt * silu(G)*I -> fp16 -> g_hh   (wt folded here)
    #pragma unroll
    for (int f = 0; f < 2; f++) {
        #pragma unroll
        for (int h = 0; h < 2; h++) {
            int r = row0 + warp_m * 32 + f * 16 + (lane >> 2) + h * 8;
            if (r >= cnt) continue;
            float wt = g_wt[e * CAP + r];
            size_t base = (size_t)(e * CAP + r) * DM;
            int col = n0 + warp_n * 32 + (lane & 3) * 2;
            #pragma unroll
            for (int n8 = 0; n8 < 4; n8++) {
                float g0 = acc[0][f][n8][2*h], g1 = acc[0][f][n8][2*h+1];
                float i0 = acc[1][f][n8][2*h], i1 = acc[1][f][n8][2*h+1];
                float v0 = wt * (g0 / (1.f + __expf(-g0)) * i0);
                float v1 = wt * (g1 / (1.f + __expf(-g1)) * i1);
                *(uint32_t*)(g_hh + base + col + n8 * 8) = packh(v0, v1);
            }
        }
    }
    #undef LDW_UP
    #undef STW_UP
    #undef CPA_T
}

// ---------------------------------------------------------------
// Down-proj + scatter: M128 x N256 tile, 16 warps, warp tile m32 x n64, BK=64.
__global__ void __launch_bounds__(512, 1)
moe_dn_kernel(const float* __restrict__ Wout, float* __restrict__ out) {
    extern __shared__ char smem[];
    uint32_t sb = smem_u32(smem);

    int e = blockIdx.z;
    int cnt = g_cnt[e];
    int row0 = blockIdx.x * 128;
    if (row0 >= cnt) return;
    int n0 = blockIdx.y * 256;

    int tid = threadIdx.x, wid = tid >> 5, lane = tid & 31;
    int warp_m = wid >> 2, warp_n = wid & 3;

    int rA = tid >> 2, q = tid & 3;
    int rowc = min(row0 + rA, cnt - 1);
    const char* gA = (const char*)(g_hh + (size_t)(e * CAP + rowc) * DM) + q * 32;
    uint32_t sA = rA * 144 + q * 32;

    // B loader: bk = tid>>4 (0..31), bn = (tid&15)*16; k's bk and bk+32
    int bk = tid >> 4, bn = (tid & 15) * 16;
    const float* pB = Wout + (size_t)e * DM * D + (size_t)bk * D + n0 + bn;
    uint32_t sB = 18432 + (uint32_t)(bn >> 6) * 9216 + bk * 144 + (bn & 63) * 2;

    uint32_t aB = sb + (warp_m * 32 + (lane & 15)) * 144 + (lane >> 4) * 16;
    uint32_t bB = sb + 18432 + warp_n * 9216 + (lane & 15) * 144 + (lane >> 4) * 16;

    float acc[2][8][4];
    #pragma unroll
    for (int a = 0; a < 2; a++)
        #pragma unroll
        for (int b = 0; b < 8; b++)
            #pragma unroll
            for (int c = 0; c < 4; c++) acc[a][b][c] = 0.f;

    const int NIT = DM / 64;   // 64
    float4 vb[8];

    #define LDW_DN(IT) do { \
        const float* _w = pB + (size_t)(IT) * 64 * D; \
        vb[0] = ldg_cg4(_w);           vb[1] = ldg_cg4(_w + 4); \
        vb[2] = ldg_cg4(_w + 8);       vb[3] = ldg_cg4(_w + 12); \
        vb[4] = ldg_cg4(_w + 32 * D);      vb[5] = ldg_cg4(_w + 32 * D + 4); \
        vb[6] = ldg_cg4(_w + 32 * D + 8);  vb[7] = ldg_cg4(_w + 32 * D + 12); \
    } while (0)

    #define STW_DN(ST) do { \
        uint4 u; \
        cv8h(vb[0], vb[1], u);  *(uint4*)(smem + (ST) + sB)              = u; \
        cv8h(vb[2], vb[3], u);  *(uint4*)(smem + (ST) + sB + 16)         = u; \
        cv8h(vb[4], vb[5], u);  *(uint4*)(smem + (ST) + sB + 4608)       = u; \
        cv8h(vb[6], vb[7], u);  *(uint4*)(smem + (ST) + sB + 4608 + 16)  = u; \
    } while (0)

    #define CPA_T(ST, IT) do { \
        const char* _a = gA + (size_t)(IT) * 128; \
        cpa16(sb + (ST) + sA, _a); \
        cpa16(sb + (ST) + sA + 16, _a + 16); \
    } while (0)

    LDW_DN(0); STW_DN(0); CPA_T(0, 0); CP_COMMIT();
    LDW_DN(1);
    CP_WAIT0();
    __syncthreads();

    for (int it = 0; it < NIT; ++it) {
        uint32_t ps = (uint32_t)(it & 1) * STAGE;
        uint32_t qs = STAGE - ps;
        bool m1 = (it + 1 < NIT);
        if (m1) { STW_DN(qs); CPA_T(qs, it + 1); }
        CP_COMMIT();
        if (it + 2 < NIT) LDW_DN(it + 2);

        #pragma unroll
        for (int kk = 0; kk < 4; kk++) {
            uint32_t A[2][4];
            #pragma unroll
            for (int f = 0; f < 2; f++)
                ldsm4(A[f], aB + ps + f * 2304 + kk * 32);
            #pragma unroll
            for (int jt = 0; jt < 4; jt++) {
                uint32_t bh[4];
                ldsm4t(bh, bB + ps + kk * 2304 + jt * 32);
                #pragma unroll
                for (int f = 0; f < 2; f++) {
                    mma16816(acc[f][2*jt],   A[f], bh[0], bh[1]);
                    mma16816(acc[f][2*jt+1], A[f], bh[2], bh[3]);
                }
            }
        }
        if (m1) CP_WAIT0();
        __syncthreads();
    }

    #pragma unroll
    for (int f = 0; f < 2; f++) {
        #pragma unroll
        for (int h = 0; h < 2; h++) {
            int r = row0 + warp_m * 32 + f * 16 + (lane >> 2) + h * 8;
            if (r >= cnt) continue;
            int tk = g_tok[e * CAP + r];
            float* po = out + (size_t)tk * D + n0 + warp_n * 64 + (lane & 3) * 2;
            #pragma unroll
            for (int n8 = 0; n8 < 8; n8++) {
                atomicAdd(po + n8 * 8,     acc[f][n8][2*h]);
                atomicAdd(po + n8 * 8 + 1, acc[f][n8][2*h + 1]);
            }
        }
    }
    #undef LDW_DN
    #undef STW_DN
    #undef CPA_T
}

// ---------------------------------------------------------------
extern "C" void kernel_launch(void* const* d_in, const int* in_sizes, int n_in,
                              void* d_out, int out_size) {
    const float* x   = (const float*)d_in[0];
    const float* Wg  = (const float*)d_in[1];
    const float* Weg = (const float*)d_in[2];
    const float* Wei = (const float*)d_in[3];
    const float* Weo = (const float*)d_in[4];
    float* out = (float*)d_out;

    static int attr_set = 0;
    if (!attr_set) {
        cudaFuncSetAttribute(moe_up_kernel, cudaFuncAttributeMaxDynamicSharedMemorySize, SMEMSZ);
        cudaFuncSetAttribute(moe_dn_kernel, cudaFuncAttributeMaxDynamicSharedMemorySize, SMEMSZ);
        attr_set = 1;
    }

    cudaMemsetAsync(out, 0, (size_t)out_size * sizeof(float));
    zero_cnt_kernel<<<1, 32>>>();
    convert_x_kernel<<<(T_TOK * D / 4) / 256, 256>>>((const float4*)x);
    router_kernel<<<T_TOK, 256>>>(x, Wg);
    moe_up_kernel<<<dim3(CAP / 128, DM / 128, E), 512, SMEMSZ>>>(Weg, Wei);
    moe_dn_kernel<<<dim3(CAP / 128, D / 256, E), 512, SMEMSZ>>>(Weo, out);
}